// round 1
// baseline (speedup 1.0000x reference)
#include <cuda_runtime.h>

// Math: softmax over a singleton axis == 1.0, so
//   out[b,q,d] = sum_k values[b,k,d]   (independent of q, queries, keys, w_score)
//
// B=4, Q=512, K=512, F=128.

#define B_ 4
#define Q_ 512
#define K_ 512
#define F_ 128
#define CHUNKS 16               // K split into 16 chunks of 32 rows
#define K_PER_CHUNK (K_ / CHUNKS)

// Scratch: partial sums per (batch, chunk, feature). 4*16*128 floats = 32 KB.
__device__ float g_partials[B_][CHUNKS][F_];

// Kernel 1: 64 blocks (b, chunk), 128 threads (one per feature d).
// Each thread sums 32 K-rows; loads are fully coalesced (128 threads * 4B = 512B/row).
__global__ void partial_sum_kernel(const float* __restrict__ values) {
    int b = blockIdx.x / CHUNKS;
    int c = blockIdx.x % CHUNKS;
    int d = threadIdx.x;

    const float* base = values + ((size_t)b * K_ + (size_t)c * K_PER_CHUNK) * F_ + d;
    float s = 0.0f;
#pragma unroll
    for (int k = 0; k < K_PER_CHUNK; ++k) {
        s += base[k * F_];
    }
    g_partials[b][c][d] = s;
}

// Kernel 2: broadcast sum-of-partials to all Q rows.
// Output is (B,Q,F) = 262144 floats = 65536 float4. One float4 per thread.
// Partials (8 KB) stay L1/L2 resident.
__global__ void broadcast_kernel(float4* __restrict__ out) {
    int idx = blockIdx.x * blockDim.x + threadIdx.x;   // [0, 65536)
    // each output row is 32 float4; rows per batch = Q_
    int d4 = idx & 31;                 // float4 index within feature dim
    int row = idx >> 5;                // global (b*Q + q)
    int b = row / Q_;

    const float4* p = reinterpret_cast<const float4*>(&g_partials[b][0][0]) + d4;
    float4 acc = p[0];
#pragma unroll
    for (int c = 1; c < CHUNKS; ++c) {
        float4 v = p[c * (F_ / 4)];
        acc.x += v.x; acc.y += v.y; acc.z += v.z; acc.w += v.w;
    }
    out[idx] = acc;
}

extern "C" void kernel_launch(void* const* d_in, const int* in_sizes, int n_in,
                              void* d_out, int out_size) {
    // inputs (metadata order): queries, keys, values, w_score
    const float* values = (const float*)d_in[2];
    float4* out = (float4*)d_out;

    partial_sum_kernel<<<B_ * CHUNKS, F_>>>(values);
    // total float4 outputs = B*Q*F/4 = 65536 -> 256 blocks * 256 threads
    broadcast_kernel<<<256, 256>>>(out);
}

// round 2
// speedup vs baseline: 1.3140x; 1.3140x over previous
#include <cuda_runtime.h>

// out[b,q,d] = sum_k values[b,k,d]  (softmax over singleton axis == 1;
// queries/keys/w_score are dead code).
// B=4, Q=512, K=512, F=128.
//
// Single fused kernel: 64 blocks = 4 batches x 16 output-slices.
// Each block redundantly computes its batch's column sum (256 KB, L2-hot
// after the first readers pull it from DRAM), then writes 32 Q-rows.

#define B_ 4
#define Q_ 512
#define K_ 512
#define F4 32                    // F/4 float4 per row
#define BLOCKS_PER_BATCH 16
#define ROWS_PER_BLOCK (Q_ / BLOCKS_PER_BATCH)   // 32
#define THREADS 512
#define REPS (THREADS / 32)      // 16 row-group replicas
#define ROWS_PER_REP (K_ / REPS) // 32

__global__ void __launch_bounds__(THREADS, 1)
fused_sum_broadcast(const float4* __restrict__ values, float4* __restrict__ out) {
    __shared__ float4 part[REPS][F4];   // 8 KB
    __shared__ float4 total[F4];

    const int b   = blockIdx.x >> 4;            // / BLOCKS_PER_BATCH
    const int blk = blockIdx.x & 15;            // % BLOCKS_PER_BATCH
    const int d4  = threadIdx.x & 31;
    const int rep = threadIdx.x >> 5;

    // Phase 1: each warp-lane-group sums 32 rows of its batch.
    const float4* p = values + ((size_t)b * K_ + (size_t)rep * ROWS_PER_REP) * F4 + d4;
    float4 acc = make_float4(0.f, 0.f, 0.f, 0.f);
#pragma unroll 8
    for (int r = 0; r < ROWS_PER_REP; ++r) {
        float4 v = p[r * F4];
        acc.x += v.x; acc.y += v.y; acc.z += v.z; acc.w += v.w;
    }
    part[rep][d4] = acc;
    __syncthreads();

    // Phase 2: warp 0 reduces the 16 replicas per feature-quad.
    if (rep == 0) {
        float4 t = part[0][d4];
#pragma unroll
        for (int i = 1; i < REPS; ++i) {
            float4 v = part[i][d4];
            t.x += v.x; t.y += v.y; t.z += v.z; t.w += v.w;
        }
        total[d4] = t;
    }
    __syncthreads();

    // Phase 3: broadcast to this block's 32 Q-rows (1024 float4, 2 per thread).
    const float4 t = total[d4];
    float4* ob = out + ((size_t)b * Q_ + (size_t)blk * ROWS_PER_BLOCK) * F4;
    ob[(rep * 2 + 0) * F4 + d4] = t;
    ob[(rep * 2 + 1) * F4 + d4] = t;
}

extern "C" void kernel_launch(void* const* d_in, const int* in_sizes, int n_in,
                              void* d_out, int out_size) {
    // inputs (metadata order): queries, keys, values, w_score
    const float4* values = (const float4*)d_in[2];
    float4* out = (float4*)d_out;
    fused_sum_broadcast<<<B_ * BLOCKS_PER_BATCH, THREADS>>>(values, out);
}